// round 10
// baseline (speedup 1.0000x reference)
#include <cuda_runtime.h>
#include <cstdint>

// ---------------------------------------------------------------------------
// VQ-VAE VectorQuantizer, GB300 sm_103.
// R10: int8 DP4A screening (whole codebook in smem) + batched bit-exact
// resolve of pixels whose approx top-2 gap < EPS (R3-style transposed FFMA2
// chains reproducing the reference fp32 semantics exactly).
// ---------------------------------------------------------------------------

constexpr int CC   = 64;
constexpr int CHW  = 4096;
constexpr int NPIX = 65536;
constexpr int KCB  = 1024;

constexpr int Q_ELEMS = 4194304;
constexpr int LOSS0   = Q_ELEMS;
constexpr int LOSS1   = Q_ELEMS + 1;
constexpr int IDX0    = Q_ELEMS + 2;

constexpr float EPS = 7.0e-4f;      // int8 gap err sigma ~9e-5 -> ~7.5 sigma

__device__ int   g_cnt;            // zero-init; reset by vq_fin each run
__device__ int   g_list[NPIX];
__device__ float g_part[256];
__device__ int   g_emb8[KCB * 16]; // int8-packed codebook (16 ints/code)
__device__ float g_scl[KCB];       // se_k = max|e_k| / 127
__device__ float g_e2a[KCB];       // approx fp32 ||e_k||^2 (scorer only)

// ---- helpers ---------------------------------------------------------------
__device__ __forceinline__ int dp4a(int a, int b, int c) {
    int d;
    asm("dp4a.s32.s32 %0, %1, %2, %3;" : "=r"(d) : "r"(a), "r"(b), "r"(c));
    return d;
}
__device__ __forceinline__ unsigned long long pack2f(float lo, float hi) {
    unsigned long long r;
    asm("mov.b64 %0, {%1, %2};" : "=l"(r) : "f"(lo), "f"(hi));
    return r;
}
__device__ __forceinline__ void unpack2f(unsigned long long v, float& lo, float& hi) {
    asm("mov.b64 {%0, %1}, %2;" : "=f"(lo), "=f"(hi) : "l"(v));
}
__device__ __forceinline__ unsigned long long ffma2(unsigned long long a,
                                                    unsigned long long b,
                                                    unsigned long long c) {
    unsigned long long d;
    asm("fma.rn.f32x2 %0, %1, %2, %3;" : "=l"(d) : "l"(a), "l"(b), "l"(c));
    return d;
}
__device__ __forceinline__ int pack8(float v0, float v1, float v2, float v3, float inv) {
    int a0 = __float2int_rn(v0 * inv);
    int a1 = __float2int_rn(v1 * inv);
    int a2 = __float2int_rn(v2 * inv);
    int a3 = __float2int_rn(v3 * inv);
    return (a0 & 0xFF) | ((a1 & 0xFF) << 8) | ((a2 & 0xFF) << 16) | (a3 << 24);
}

// ---- K0: quantize codebook to int8, store scale + approx e2 ----------------
__global__ void __launch_bounds__(256)
vq_init(const float* __restrict__ emb) {
    int k = blockIdx.x * 256 + threadIdx.x;
    if (k >= KCB) return;
    const float4* er = reinterpret_cast<const float4*>(emb + (size_t)k * CC);
    float v[CC];
    #pragma unroll
    for (int i = 0; i < 16; i++) {
        float4 t = er[i];
        v[4*i] = t.x; v[4*i+1] = t.y; v[4*i+2] = t.z; v[4*i+3] = t.w;
    }
    float ma = 0.f, e2 = 0.f;
    #pragma unroll
    for (int c = 0; c < CC; c++) ma = fmaxf(ma, fabsf(v[c]));
    #pragma unroll
    for (int c = 0; c < CC; c++) e2 += v[c] * v[c];
    float inv = (ma > 1e-30f) ? 127.0f / ma : 0.f;
    int* dst = g_emb8 + k * 16;
    #pragma unroll
    for (int g = 0; g < 16; g++)
        dst[g] = pack8(v[4*g], v[4*g+1], v[4*g+2], v[4*g+3], inv);
    g_scl[k] = ma * (1.0f / 127.0f);
    g_e2a[k] = e2;
}

// ---- K1: DP4A approximate argmin + flagging --------------------------------
__global__ void __launch_bounds__(256)
vq_score(const float* __restrict__ z, float* __restrict__ out) {
    extern __shared__ char smem[];
    int4*  cb  = reinterpret_cast<int4*>(smem);            // 1024*16 int = 64KB
    float* scl = reinterpret_cast<float*>(smem + 65536);   // 4KB
    float* e2a = scl + KCB;                                // 4KB

    const int tid = threadIdx.x;
    const int4* gcb = reinterpret_cast<const int4*>(g_emb8);
    #pragma unroll
    for (int i = 0; i < 16; i++) cb[tid + i * 256] = gcb[tid + i * 256];
    #pragma unroll
    for (int i = 0; i < 4; i++) {
        scl[tid + i * 256] = g_scl[tid + i * 256];
        e2a[tid + i * 256] = g_e2a[tid + i * 256];
    }
    __syncthreads();

    const int p  = blockIdx.x * 256 + tid;
    const int b  = p >> 12, hw = p & 4095;
    const float* zp = z + (size_t)b * (CC * CHW) + hw;

    float zv[CC];
    #pragma unroll
    for (int c = 0; c < CC; c++) zv[c] = zp[c * CHW];
    float ma = 0.f;
    #pragma unroll
    for (int c = 0; c < CC; c++) ma = fmaxf(ma, fabsf(zv[c]));
    float inv = (ma > 1e-30f) ? 127.0f / ma : 0.f;
    int qz[16];
    #pragma unroll
    for (int g = 0; g < 16; g++)
        qz[g] = pack8(zv[4*g], zv[4*g+1], zv[4*g+2], zv[4*g+3], inv);
    const float sz2 = -2.0f * ma * (1.0f / 127.0f);   // -2*sz

    float b1 = 3.4e38f, b2 = 3.4e38f;
    int   k1 = 0;

    #pragma unroll 1
    for (int k = 0; k < KCB; k += 2) {
        const int4* c0 = cb + k * 4;
        int4 u0 = c0[0], u1 = c0[1], u2 = c0[2], u3 = c0[3];
        int4 w0 = c0[4], w1 = c0[5], w2 = c0[6], w3 = c0[7];
        int iA = 0, iB = 0, jA = 0, jB = 0;
        iA = dp4a(u0.x, qz[0], iA);  iA = dp4a(u0.y, qz[1], iA);
        iA = dp4a(u0.z, qz[2], iA);  iA = dp4a(u0.w, qz[3], iA);
        iA = dp4a(u1.x, qz[4], iA);  iA = dp4a(u1.y, qz[5], iA);
        iA = dp4a(u1.z, qz[6], iA);  iA = dp4a(u1.w, qz[7], iA);
        iB = dp4a(u2.x, qz[8], iB);  iB = dp4a(u2.y, qz[9], iB);
        iB = dp4a(u2.z, qz[10], iB); iB = dp4a(u2.w, qz[11], iB);
        iB = dp4a(u3.x, qz[12], iB); iB = dp4a(u3.y, qz[13], iB);
        iB = dp4a(u3.z, qz[14], iB); iB = dp4a(u3.w, qz[15], iB);
        jA = dp4a(w0.x, qz[0], jA);  jA = dp4a(w0.y, qz[1], jA);
        jA = dp4a(w0.z, qz[2], jA);  jA = dp4a(w0.w, qz[3], jA);
        jA = dp4a(w1.x, qz[4], jA);  jA = dp4a(w1.y, qz[5], jA);
        jA = dp4a(w1.z, qz[6], jA);  jA = dp4a(w1.w, qz[7], jA);
        jB = dp4a(w2.x, qz[8], jB);  jB = dp4a(w2.y, qz[9], jB);
        jB = dp4a(w2.z, qz[10], jB); jB = dp4a(w2.w, qz[11], jB);
        jB = dp4a(w3.x, qz[12], jB); jB = dp4a(w3.y, qz[13], jB);
        jB = dp4a(w3.z, qz[14], jB); jB = dp4a(w3.w, qz[15], jB);

        float f0 = __int2float_rn(iA + iB);
        float f1 = __int2float_rn(jA + jB);
        float s0 = __fmaf_rn(sz2, f0 * scl[k],     e2a[k]);
        float s1 = __fmaf_rn(sz2, f1 * scl[k + 1], e2a[k + 1]);
        if (s0 < b1)      { b2 = b1; b1 = s0; k1 = k; }
        else if (s0 < b2) { b2 = s0; }
        if (s1 < b1)      { b2 = b1; b1 = s1; k1 = k + 1; }
        else if (s1 < b2) { b2 = s1; }
    }

    out[IDX0 + p] = (float)k1;
    if (b2 - b1 < EPS) {
        int pos = atomicAdd(&g_cnt, 1);
        g_list[pos] = p;
    }
}

// ---- K2: batched bit-exact resolve (reference fp32 chain semantics) --------
// 64 flagged pixels per block pass: 32 pairs x 8 code-split threads.
__global__ void __launch_bounds__(256)
vq_exact(const float* __restrict__ z, const float* __restrict__ emb,
         float* __restrict__ out) {
    __shared__ __align__(16) float eT[CC * 132];  // transposed chunk [c][k]
    __shared__ float e2s[128];

    const int tid = threadIdx.x;
    const int q = tid >> 3, t = tid & 7;
    const int n = g_cnt;
    if (n == 0) return;
    const int n1 = n - 1;

    for (int base = blockIdx.x * 64; base < n; base += gridDim.x * 64) {
        const int p0 = g_list[min(base + q, n1)];
        const int p1 = g_list[min(base + 32 + q, n1)];
        const float* zp0 = z + (size_t)(p0 >> 12) * (CC * CHW) + (p0 & 4095);
        const float* zp1 = z + (size_t)(p1 >> 12) * (CC * CHW) + (p1 & 4095);

        float zr0[CC], zr1[CC];
        #pragma unroll
        for (int c = 0; c < CC; c++) zr0[c] = zp0[c * CHW];
        #pragma unroll
        for (int c = 0; c < CC; c++) zr1[c] = zp1[c * CHW];

        float zz0 = 0.f, zz1 = 0.f;
        #pragma unroll
        for (int c = 0; c < CC; c++) zz0 = __fadd_rn(zz0, __fmul_rn(zr0[c], zr0[c]));
        #pragma unroll
        for (int c = 0; c < CC; c++) zz1 = __fadd_rn(zz1, __fmul_rn(zr1[c], zr1[c]));

        float bv0 = 3.4e38f, bv1 = 3.4e38f;
        int   bk0 = 0, bk1 = 0;

        for (int ch = 0; ch < 8; ch++) {
            __syncthreads();          // prior chunk fully consumed / group done
            const float* ebase = emb + ch * 128 * CC;
            #pragma unroll
            for (int it = 0; it < 2; it++) {
                int idx = tid + it * 256;
                int k0 = (idx & 31) * 4;
                int c0 = (idx >> 5) * 4;
                float4 r0 = *reinterpret_cast<const float4*>(ebase + (k0 + 0) * CC + c0);
                float4 r1 = *reinterpret_cast<const float4*>(ebase + (k0 + 1) * CC + c0);
                float4 r2 = *reinterpret_cast<const float4*>(ebase + (k0 + 2) * CC + c0);
                float4 r3 = *reinterpret_cast<const float4*>(ebase + (k0 + 3) * CC + c0);
                *reinterpret_cast<float4*>(eT + (c0 + 0) * 132 + k0) = make_float4(r0.x, r1.x, r2.x, r3.x);
                *reinterpret_cast<float4*>(eT + (c0 + 1) * 132 + k0) = make_float4(r0.y, r1.y, r2.y, r3.y);
                *reinterpret_cast<float4*>(eT + (c0 + 2) * 132 + k0) = make_float4(r0.z, r1.z, r2.z, r3.z);
                *reinterpret_cast<float4*>(eT + (c0 + 3) * 132 + k0) = make_float4(r0.w, r1.w, r2.w, r3.w);
            }
            __syncthreads();
            if (tid < 128) {          // exact e2 chain per code
                float s = 0.f;
                #pragma unroll
                for (int c = 0; c < CC; c++) {
                    float ev = eT[c * 132 + tid];
                    s = __fadd_rn(s, __fmul_rn(ev, ev));
                }
                e2s[tid] = s;
            }
            __syncthreads();

            unsigned long long a0[8], a1[8];
            #pragma unroll
            for (int i = 0; i < 8; i++) { a0[i] = 0ull; a1[i] = 0ull; }
            const char* rowp = reinterpret_cast<const char*>(eT + t * 16);
            #pragma unroll
            for (int c = 0; c < CC; c++) {
                unsigned long long zd0 = pack2f(zr0[c], zr0[c]);
                unsigned long long zd1 = pack2f(zr1[c], zr1[c]);
                const ulonglong2* qp = reinterpret_cast<const ulonglong2*>(rowp + c * 528);
                #pragma unroll
                for (int m = 0; m < 4; m++) {
                    ulonglong2 v = qp[m];
                    a0[2*m]   = ffma2(zd0, v.x, a0[2*m]);
                    a0[2*m+1] = ffma2(zd0, v.y, a0[2*m+1]);
                    a1[2*m]   = ffma2(zd1, v.x, a1[2*m]);
                    a1[2*m+1] = ffma2(zd1, v.y, a1[2*m+1]);
                }
            }
            const int kb = ch * 128 + t * 16;
            #pragma unroll
            for (int m = 0; m < 4; m++) {
                float d0[4], d1[4];
                unpack2f(a0[2*m], d0[0], d0[1]); unpack2f(a0[2*m+1], d0[2], d0[3]);
                unpack2f(a1[2*m], d1[0], d1[1]); unpack2f(a1[2*m+1], d1[2], d1[3]);
                #pragma unroll
                for (int j = 0; j < 4; j++) {
                    float e2 = e2s[t * 16 + 4 * m + j];
                    int   kk = kb + 4 * m + j;
                    float s0 = __fsub_rn(__fadd_rn(zz0, e2), __fmul_rn(2.0f, d0[j]));
                    float s1 = __fsub_rn(__fadd_rn(zz1, e2), __fmul_rn(2.0f, d1[j]));
                    if (s0 < bv0) { bv0 = s0; bk0 = kk; }
                    if (s1 < bv1) { bv1 = s1; bk1 = kk; }
                }
            }
        }

        // lexicographic merge over the 8 code-split threads of each pair
        #pragma unroll
        for (int off = 1; off < 8; off <<= 1) {
            float ov0 = __shfl_xor_sync(0xffffffffu, bv0, off);
            int   ok0 = __shfl_xor_sync(0xffffffffu, bk0, off);
            float ov1 = __shfl_xor_sync(0xffffffffu, bv1, off);
            int   ok1 = __shfl_xor_sync(0xffffffffu, bk1, off);
            if (ov0 < bv0 || (ov0 == bv0 && ok0 < bk0)) { bv0 = ov0; bk0 = ok0; }
            if (ov1 < bv1 || (ov1 == bv1 && ok1 < bk1)) { bv1 = ov1; bk1 = ok1; }
        }
        if (t == 0) {
            out[IDX0 + p0] = (float)bk0;
            out[IDX0 + p1] = (float)bk1;
        }
    }
}

// ---- K3: emit q + loss partials from final idx -----------------------------
__global__ void __launch_bounds__(256)
vq_emit(const float* __restrict__ z, const float* __restrict__ emb,
        float* __restrict__ out) {
    __shared__ float reds[8];
    const int p = blockIdx.x * 256 + threadIdx.x;
    const int b = p >> 12, hw = p & 4095;
    const int k = (int)out[IDX0 + p];
    const float4* er = reinterpret_cast<const float4*>(emb + (size_t)k * CC);
    const float* zp = z + (size_t)b * (CC * CHW) + hw;
    float* qp = out + (size_t)b * (CC * CHW) + hw;

    float sumsq = 0.f;
    #pragma unroll
    for (int i = 0; i < 16; i++) {
        float4 e4 = __ldg(er + i);
        float ev[4] = {e4.x, e4.y, e4.z, e4.w};
        #pragma unroll
        for (int j = 0; j < 4; j++) {
            int c = 4 * i + j;
            float zv = zp[c * CHW];
            float dd = __fsub_rn(ev[j], zv);
            sumsq = __fadd_rn(sumsq, __fmul_rn(dd, dd));
            qp[c * CHW] = __fadd_rn(zv, dd);          // fl(z + fl(e - z))
        }
    }
    #pragma unroll
    for (int o = 16; o; o >>= 1)
        sumsq += __shfl_xor_sync(0xffffffffu, sumsq, o);
    if ((threadIdx.x & 31) == 0) reds[threadIdx.x >> 5] = sumsq;
    __syncthreads();
    if (threadIdx.x == 0) {
        float s = 0.f;
        #pragma unroll
        for (int w = 0; w < 8; w++) s += reds[w];
        g_part[blockIdx.x] = s;
    }
}

// ---- K4: finalize losses, reset worklist -----------------------------------
__global__ void __launch_bounds__(256)
vq_fin(float* __restrict__ out) {
    __shared__ float reds[8];
    const int tid = threadIdx.x;
    float s = g_part[tid];
    #pragma unroll
    for (int o = 16; o; o >>= 1)
        s += __shfl_xor_sync(0xffffffffu, s, o);
    if ((tid & 31) == 0) reds[tid >> 5] = s;
    __syncthreads();
    if (tid == 0) {
        float t = 0.f;
        #pragma unroll
        for (int w = 0; w < 8; w++) t += reds[w];
        float loss = t * (1.0f / (float)Q_ELEMS);
        out[LOSS0] = loss;
        out[LOSS1] = loss;
        g_cnt = 0;
    }
}

extern "C" void kernel_launch(void* const* d_in, const int* in_sizes, int n_in,
                              void* d_out, int out_size) {
    const float* z   = (const float*)d_in[0];
    const float* emb = (const float*)d_in[1];
    float* out = (float*)d_out;

    constexpr int SCORE_SMEM = 65536 + 2 * KCB * 4;   // 73728 B
    cudaFuncSetAttribute(vq_score, cudaFuncAttributeMaxDynamicSharedMemorySize,
                         SCORE_SMEM);

    vq_init<<<4, 256>>>(emb);
    vq_score<<<NPIX / 256, 256, SCORE_SMEM>>>(z, out);
    vq_exact<<<148, 256>>>(z, emb, out);
    vq_emit<<<NPIX / 256, 256>>>(z, emb, out);
    vq_fin<<<1, 256>>>(out);
}

// round 11
// speedup vs baseline: 1.2120x; 1.2120x over previous
#include <cuda_runtime.h>
#include <cuda_fp16.h>
#include <cstdint>

// ---------------------------------------------------------------------------
// VQ-VAE VectorQuantizer, GB300 sm_103.
// R11: fp16 HFMA2 screen (panel-format codebook, 4 sub-accumulators per code
// for bounded fp16 accumulation error) + fused q/loss emit for confidently
// decided pixels; pixels with approx top-2 gap < EPS resolved by the proven
// batched bit-exact kernel (reference fp32 chain semantics, first-min ties).
// ---------------------------------------------------------------------------

constexpr int CC   = 64;
constexpr int CHW  = 4096;
constexpr int NPIX = 65536;
constexpr int KCB  = 1024;

constexpr int Q_ELEMS = 4194304;
constexpr int LOSS0   = Q_ELEMS;
constexpr int LOSS1   = Q_ELEMS + 1;
constexpr int IDX0    = Q_ELEMS + 2;

constexpr float EPS      = 2.0e-4f;   // fp16 gap-err sigma ~1.5e-5 -> ~13 sigma
constexpr float INV_QE   = 1.0f / (float)Q_ELEMS;

__device__ int   g_cnt;                       // zero-init; reset by vq_fin
__device__ int   g_list[NPIX];
__device__ __align__(16) __half g_embh[KCB * CC];  // panel layout [k/8][c][k%8]
__device__ float g_e2[KCB];                   // fp32 ||e_k||^2 (screen use)

// ---- helpers ---------------------------------------------------------------
__device__ __forceinline__ unsigned long long pack2f(float lo, float hi) {
    unsigned long long r;
    asm("mov.b64 %0, {%1, %2};" : "=l"(r) : "f"(lo), "f"(hi));
    return r;
}
__device__ __forceinline__ void unpack2f(unsigned long long v, float& lo, float& hi) {
    asm("mov.b64 {%0, %1}, %2;" : "=f"(lo), "=f"(hi) : "l"(v));
}
__device__ __forceinline__ unsigned long long ffma2(unsigned long long a,
                                                    unsigned long long b,
                                                    unsigned long long c) {
    unsigned long long d;
    asm("fma.rn.f32x2 %0, %1, %2, %3;" : "=l"(d) : "l"(a), "l"(b), "l"(c));
    return d;
}

// ---- K0: fp16 panel-format codebook + fp32 norms + zero loss ---------------
__global__ void __launch_bounds__(128)
vq_init(const float* __restrict__ emb, float* __restrict__ out) {
    int k = blockIdx.x * 128 + threadIdx.x;   // 8 blocks x 128 = 1024
    if (k < KCB) {
        const float4* er = reinterpret_cast<const float4*>(emb + (size_t)k * CC);
        float v[CC];
        #pragma unroll
        for (int i = 0; i < 16; i++) {
            float4 t = er[i];
            v[4*i] = t.x; v[4*i+1] = t.y; v[4*i+2] = t.z; v[4*i+3] = t.w;
        }
        float e2 = 0.f;
        #pragma unroll
        for (int c = 0; c < CC; c++) e2 += v[c] * v[c];
        g_e2[k] = e2;
        __half* dst = g_embh + (k >> 3) * 512 + (k & 7);
        #pragma unroll
        for (int c = 0; c < CC; c++) dst[c * 8] = __float2half_rn(v[c]);
    }
    if (k == 0) out[LOSS0] = 0.f;
}

// ---- K1: fp16 screen + fused emit for confident pixels ---------------------
__global__ void __launch_bounds__(256, 2)
vq_screen(const float* __restrict__ z, const float* __restrict__ emb,
          float* __restrict__ out) {
    __shared__ __align__(16) __half hs[16384];  // 256 codes x 64 c, panel fmt
    __shared__ float e2s[256];

    const int tid  = threadIdx.x;
    const int px   = blockIdx.x * 256 + tid;
    const int b    = px >> 12, hw = px & 4095;
    const float* zp = z + (size_t)b * (CC * CHW) + hw;

    // z in fp16 broadcast pairs (z_c, z_c)
    __half2 zb[CC];
    #pragma unroll
    for (int c = 0; c < CC; c++)
        zb[c] = __half2half2(__float2half_rn(zp[c * CHW]));

    float b1 = 3.4e38f, b2 = 3.4e38f;
    int   k1 = 0;

    for (int ch = 0; ch < 4; ch++) {
        __syncthreads();
        // stage 256-code chunk (32 KB) + norms
        const uint4* src = reinterpret_cast<const uint4*>(g_embh) + ch * 2048;
        uint4* dst = reinterpret_cast<uint4*>(hs);
        #pragma unroll
        for (int i = 0; i < 8; i++) dst[tid + i * 256] = src[tid + i * 256];
        e2s[tid] = g_e2[ch * 256 + tid];
        __syncthreads();

        #pragma unroll 1
        for (int p = 0; p < 32; p++) {          // panel = 8 codes
            const uint4* r4 = reinterpret_cast<const uint4*>(hs + p * 512);
            __half2 acc[4][4];                   // [code-pair][16-chan subacc]
            #pragma unroll
            for (int q = 0; q < 4; q++)
                #pragma unroll
                for (int s = 0; s < 4; s++)
                    acc[q][s] = __half2half2(__float2half_rn(0.f));
            #pragma unroll
            for (int c = 0; c < CC; c++) {
                uint4 u = r4[c];                 // LDS.128 broadcast
                __half2 v0 = *reinterpret_cast<__half2*>(&u.x);
                __half2 v1 = *reinterpret_cast<__half2*>(&u.y);
                __half2 v2 = *reinterpret_cast<__half2*>(&u.z);
                __half2 v3 = *reinterpret_cast<__half2*>(&u.w);
                const int s = c >> 4;
                acc[0][s] = __hfma2(zb[c], v0, acc[0][s]);
                acc[1][s] = __hfma2(zb[c], v1, acc[1][s]);
                acc[2][s] = __hfma2(zb[c], v2, acc[2][s]);
                acc[3][s] = __hfma2(zb[c], v3, acc[3][s]);
            }
            const int kb = ch * 256 + p * 8;
            #pragma unroll
            for (int q = 0; q < 4; q++) {
                __half2 hsum = __hadd2(__hadd2(acc[q][0], acc[q][1]),
                                       __hadd2(acc[q][2], acc[q][3]));
                float s0 = fmaf(-2.f, __low2float(hsum),  e2s[p * 8 + 2 * q]);
                float s1 = fmaf(-2.f, __high2float(hsum), e2s[p * 8 + 2 * q + 1]);
                if (s0 < b1)      { b2 = b1; b1 = s0; k1 = kb + 2 * q; }
                else if (s0 < b2) { b2 = s0; }
                if (s1 < b1)      { b2 = b1; b1 = s1; k1 = kb + 2 * q + 1; }
                else if (s1 < b2) { b2 = s1; }
            }
        }
    }

    out[IDX0 + px] = (float)k1;                  // overwritten later if flagged
    const bool flag = (b2 - b1 < EPS);
    float sumsq = 0.f;
    if (!flag) {
        // fused emit: q = fl(z + fl(e - z)), loss partial
        const float4* er = reinterpret_cast<const float4*>(emb + (size_t)k1 * CC);
        float* qp = out + (size_t)b * (CC * CHW) + hw;
        #pragma unroll
        for (int i = 0; i < 16; i++) {
            float4 e4 = __ldg(er + i);
            float ev[4] = {e4.x, e4.y, e4.z, e4.w};
            #pragma unroll
            for (int j = 0; j < 4; j++) {
                int c = 4 * i + j;
                float zv = zp[c * CHW];
                float dd = __fsub_rn(ev[j], zv);
                sumsq = fmaf(dd, dd, sumsq);
                qp[c * CHW] = __fadd_rn(zv, dd);
            }
        }
    } else {
        int pos = atomicAdd(&g_cnt, 1);
        g_list[pos] = px;
    }
    #pragma unroll
    for (int o = 16; o; o >>= 1)
        sumsq += __shfl_xor_sync(0xffffffffu, sumsq, o);
    if ((tid & 31) == 0 && sumsq != 0.f)
        atomicAdd(&out[LOSS0], sumsq * INV_QE);
}

// ---- K2: batched bit-exact resolve + emit for flagged pixels ---------------
// 32 pixels per block-pass: 32 slots x 8 code-split threads.
__global__ void __launch_bounds__(256)
vq_exact(const float* __restrict__ z, const float* __restrict__ emb,
         float* __restrict__ out) {
    __shared__ __align__(16) float eT[CC * 132];  // transposed chunk [c][k]
    __shared__ float e2s[128];

    const int tid = threadIdx.x;
    const int q = tid >> 3, t = tid & 7;
    const int n = g_cnt;
    if (blockIdx.x * 32 >= n) return;

    for (int base = blockIdx.x * 32; base < n; base += gridDim.x * 32) {
        __syncthreads();
        const bool active = (base + q) < n;
        const int  p  = g_list[active ? (base + q) : 0];
        const int  pb = p >> 12, phw = p & 4095;
        const float* zp = z + (size_t)pb * (CC * CHW) + phw;

        float zr[CC];
        #pragma unroll
        for (int c = 0; c < CC; c++) zr[c] = zp[c * CHW];

        float zz = 0.f;
        #pragma unroll
        for (int c = 0; c < CC; c++) zz = __fadd_rn(zz, __fmul_rn(zr[c], zr[c]));

        float bv = 3.4e38f; int bk = 0;

        for (int ch = 0; ch < 8; ch++) {
            __syncthreads();
            const float* ebase = emb + ch * 128 * CC;
            #pragma unroll
            for (int it = 0; it < 2; it++) {
                int idx = tid + it * 256;
                int k0 = (idx & 31) * 4;
                int c0 = (idx >> 5) * 4;
                float4 r0 = *reinterpret_cast<const float4*>(ebase + (k0 + 0) * CC + c0);
                float4 r1 = *reinterpret_cast<const float4*>(ebase + (k0 + 1) * CC + c0);
                float4 r2 = *reinterpret_cast<const float4*>(ebase + (k0 + 2) * CC + c0);
                float4 r3 = *reinterpret_cast<const float4*>(ebase + (k0 + 3) * CC + c0);
                *reinterpret_cast<float4*>(eT + (c0 + 0) * 132 + k0) = make_float4(r0.x, r1.x, r2.x, r3.x);
                *reinterpret_cast<float4*>(eT + (c0 + 1) * 132 + k0) = make_float4(r0.y, r1.y, r2.y, r3.y);
                *reinterpret_cast<float4*>(eT + (c0 + 2) * 132 + k0) = make_float4(r0.z, r1.z, r2.z, r3.z);
                *reinterpret_cast<float4*>(eT + (c0 + 3) * 132 + k0) = make_float4(r0.w, r1.w, r2.w, r3.w);
            }
            __syncthreads();
            if (tid < 128) {                       // exact e2 chain per code
                float s = 0.f;
                #pragma unroll
                for (int c = 0; c < CC; c++) {
                    float ev = eT[c * 132 + tid];
                    s = __fadd_rn(s, __fmul_rn(ev, ev));
                }
                e2s[tid] = s;
            }
            __syncthreads();

            unsigned long long a[8];
            #pragma unroll
            for (int i = 0; i < 8; i++) a[i] = 0ull;
            const char* rowp = reinterpret_cast<const char*>(eT + t * 16);
            #pragma unroll
            for (int c = 0; c < CC; c++) {
                unsigned long long zd = pack2f(zr[c], zr[c]);
                const ulonglong2* qp = reinterpret_cast<const ulonglong2*>(rowp + c * 528);
                #pragma unroll
                for (int m = 0; m < 4; m++) {
                    ulonglong2 v = qp[m];
                    a[2*m]   = ffma2(zd, v.x, a[2*m]);
                    a[2*m+1] = ffma2(zd, v.y, a[2*m+1]);
                }
            }
            const int kb = ch * 128 + t * 16;
            #pragma unroll
            for (int m = 0; m < 4; m++) {
                float d[4];
                unpack2f(a[2*m], d[0], d[1]);
                unpack2f(a[2*m+1], d[2], d[3]);
                #pragma unroll
                for (int j = 0; j < 4; j++) {
                    float e2 = e2s[t * 16 + 4 * m + j];
                    float s  = __fsub_rn(__fadd_rn(zz, e2), __fmul_rn(2.0f, d[j]));
                    if (s < bv) { bv = s; bk = kb + 4 * m + j; }  // k ascending
                }
            }
        }

        // lexicographic first-min merge over the 8 code-split threads
        #pragma unroll
        for (int off = 1; off < 8; off <<= 1) {
            float ov = __shfl_xor_sync(0xffffffffu, bv, off);
            int   ok = __shfl_xor_sync(0xffffffffu, bk, off);
            if (ov < bv || (ov == bv && ok < bk)) { bv = ov; bk = ok; }
        }

        // emit q + loss for this pixel (8 threads x 8 channels)
        float sumsq = 0.f;
        if (active) {
            const float4* er = reinterpret_cast<const float4*>(emb + (size_t)bk * CC + t * 8);
            float* qp = out + (size_t)pb * (CC * CHW) + phw;
            #pragma unroll
            for (int i = 0; i < 2; i++) {
                float4 e4 = __ldg(er + i);
                float ev[4] = {e4.x, e4.y, e4.z, e4.w};
                #pragma unroll
                for (int j = 0; j < 4; j++) {
                    int c = t * 8 + 4 * i + j;
                    float dd = __fsub_rn(ev[j], zr[c]);
                    sumsq = fmaf(dd, dd, sumsq);
                    qp[c * CHW] = __fadd_rn(zr[c], dd);
                }
            }
            if (t == 0) out[IDX0 + p] = (float)bk;
        }
        #pragma unroll
        for (int off = 1; off < 8; off <<= 1)
            sumsq += __shfl_xor_sync(0xffffffffu, sumsq, off);
        if (t == 0 && active)
            atomicAdd(&out[LOSS0], sumsq * INV_QE);
    }
}

// ---- K3: finalize (duplicate loss), reset worklist -------------------------
__global__ void vq_fin(float* __restrict__ out) {
    if (threadIdx.x == 0) {
        out[LOSS1] = out[LOSS0];
        g_cnt = 0;
    }
}

extern "C" void kernel_launch(void* const* d_in, const int* in_sizes, int n_in,
                              void* d_out, int out_size) {
    const float* z   = (const float*)d_in[0];
    const float* emb = (const float*)d_in[1];
    float* out = (float*)d_out;

    vq_init<<<8, 128>>>(emb, out);
    vq_screen<<<NPIX / 256, 256>>>(z, emb, out);
    vq_exact<<<296, 256>>>(z, emb, out);
    vq_fin<<<1, 32>>>(out);
}

// round 13
// speedup vs baseline: 1.9608x; 1.6178x over previous
#include <cuda_runtime.h>
#include <cstdint>

// ---------------------------------------------------------------------------
// VQ-VAE VectorQuantizer, GB300 sm_103 — bit-exact fp32 reference emulation.
// R13 = R12 resubmit (R12 bench was an infra failure, no signal).
// R3 main kernel (proven, 215us, at FFMA2 RF-banking floor) with overhead
// removed: per-code ||e||^2 computed in-block from the transposed smem tile
// (kills the 13us vq_init launch), parallel loss finalize.
//   zz   = sequential fp32 mul+add over c (ascending)
//   e2_k = sequential fp32 mul+add over c (ascending)
//   dot_k= sequential fp32 FMA chain over c (ascending)
//   d_k  = fl(fl(zz + e2_k) - fl(2*dot_k)); argmin first-min, k ascending
//   q    = fl(z + fl(e - z))
// ---------------------------------------------------------------------------

constexpr int CC     = 64;           // channels
constexpr int CHW    = 4096;         // H*W
constexpr int NPIX   = 65536;        // B*H*W
constexpr int KCB    = 1024;         // codebook entries
constexpr int CHUNK  = 128;          // codes per smem chunk
constexpr int NCHUNK = KCB / CHUNK;  // 8
constexpr int NTHR   = 256;
constexpr int PZ     = 2;            // pixels per thread
constexpr int PIXBLK = NTHR * PZ;    // 512 pixels per block
constexpr int NBLK   = NPIX / PIXBLK;// 128
constexpr int RS     = 132;          // e_T row stride in floats (pad)

constexpr int Q_ELEMS = 4194304;
constexpr int LOSS0   = Q_ELEMS;
constexpr int LOSS1   = Q_ELEMS + 1;
constexpr int IDX0    = Q_ELEMS + 2;

__device__ float g_part[NBLK];

// ---- packed f32x2 helpers --------------------------------------------------
__device__ __forceinline__ unsigned long long pack2f(float lo, float hi) {
    unsigned long long r;
    asm("mov.b64 %0, {%1, %2};" : "=l"(r) : "f"(lo), "f"(hi));
    return r;
}
__device__ __forceinline__ void unpack2f(unsigned long long v, float& lo, float& hi) {
    asm("mov.b64 {%0, %1}, %2;" : "=f"(lo), "=f"(hi) : "l"(v));
}
__device__ __forceinline__ unsigned long long ffma2(unsigned long long a,
                                                    unsigned long long b,
                                                    unsigned long long c) {
    unsigned long long d;
    asm("fma.rn.f32x2 %0, %1, %2, %3;" : "=l"(d) : "l"(a), "l"(b), "l"(c));
    return d;
}

// ---- main ------------------------------------------------------------------
__global__ __launch_bounds__(NTHR)
void vq_main(const float* __restrict__ z, const float* __restrict__ emb,
             float* __restrict__ out) {
    __shared__ __align__(16) float eT[CC * RS];   // transposed chunk [c][k]
    __shared__ float e2s[CHUNK];
    __shared__ float reds[NTHR / 32];

    // two pixels per thread: p0 = base + tid, p1 = p0 + NTHR
    const int p0  = blockIdx.x * PIXBLK + threadIdx.x;
    const int p1  = p0 + NTHR;
    const int b0  = p0 >> 12, hw0 = p0 & 4095;
    const int b1  = p1 >> 12, hw1 = p1 & 4095;
    const float* zp0 = z + (size_t)b0 * (CC * CHW) + hw0;
    const float* zp1 = z + (size_t)b1 * (CC * CHW) + hw1;

    float zr0[CC], zr1[CC];
    #pragma unroll
    for (int c = 0; c < CC; c++) zr0[c] = zp0[c * CHW];
    #pragma unroll
    for (int c = 0; c < CC; c++) zr1[c] = zp1[c * CHW];

    // ||z||^2 in exact reference order
    float zz0 = 0.f, zz1 = 0.f;
    #pragma unroll
    for (int c = 0; c < CC; c++) zz0 = __fadd_rn(zz0, __fmul_rn(zr0[c], zr0[c]));
    #pragma unroll
    for (int c = 0; c < CC; c++) zz1 = __fadd_rn(zz1, __fmul_rn(zr1[c], zr1[c]));

    float best0 = 3.4e38f, best1 = 3.4e38f;
    int   bk0 = 0, bk1 = 0;

    for (int ch = 0; ch < NCHUNK; ch++) {
        if (ch) __syncthreads();
        // ---- load + transpose chunk into eT[c][k] -------------------------
        const float* ebase = emb + ch * CHUNK * CC;
        #pragma unroll
        for (int it = 0; it < 2; it++) {
            int idx = threadIdx.x + it * NTHR;   // 0..511
            int k0  = (idx & 31) * 4;
            int c0  = (idx >> 5) * 4;
            float4 r0 = *reinterpret_cast<const float4*>(ebase + (k0 + 0) * CC + c0);
            float4 r1 = *reinterpret_cast<const float4*>(ebase + (k0 + 1) * CC + c0);
            float4 r2 = *reinterpret_cast<const float4*>(ebase + (k0 + 2) * CC + c0);
            float4 r3 = *reinterpret_cast<const float4*>(ebase + (k0 + 3) * CC + c0);
            *reinterpret_cast<float4*>(eT + (c0 + 0) * RS + k0) = make_float4(r0.x, r1.x, r2.x, r3.x);
            *reinterpret_cast<float4*>(eT + (c0 + 1) * RS + k0) = make_float4(r0.y, r1.y, r2.y, r3.y);
            *reinterpret_cast<float4*>(eT + (c0 + 2) * RS + k0) = make_float4(r0.z, r1.z, r2.z, r3.z);
            *reinterpret_cast<float4*>(eT + (c0 + 3) * RS + k0) = make_float4(r0.w, r1.w, r2.w, r3.w);
        }
        __syncthreads();
        // ---- exact e2 chain per code (reference mul+add order, c asc) -----
        if (threadIdx.x < CHUNK) {
            float s = 0.f;
            #pragma unroll
            for (int c = 0; c < CC; c++) {
                float ev = eT[c * RS + threadIdx.x];   // conflict-free
                s = __fadd_rn(s, __fmul_rn(ev, ev));
            }
            e2s[threadIdx.x] = s;
        }
        __syncthreads();

        // ---- 16 groups of 8 codes; 4 f32x2 chains per pixel ---------------
        #pragma unroll 1
        for (int kg = 0; kg < CHUNK / 8; kg++) {
            unsigned long long a00 = 0ull, a01 = 0ull, a02 = 0ull, a03 = 0ull;
            unsigned long long a10 = 0ull, a11 = 0ull, a12 = 0ull, a13 = 0ull;
            const char* rowp = reinterpret_cast<const char*>(eT + kg * 8);
            #pragma unroll
            for (int c = 0; c < CC; c++) {
                const ulonglong2* q =
                    reinterpret_cast<const ulonglong2*>(rowp + c * (RS * 4));
                ulonglong2 v0 = q[0];   // codes k..k+3   (broadcast LDS.128)
                ulonglong2 v1 = q[1];   // codes k+4..k+7
                unsigned long long zd0 = pack2f(zr0[c], zr0[c]);
                unsigned long long zd1 = pack2f(zr1[c], zr1[c]);
                a00 = ffma2(zd0, v0.x, a00);
                a01 = ffma2(zd0, v0.y, a01);
                a02 = ffma2(zd0, v1.x, a02);
                a03 = ffma2(zd0, v1.y, a03);
                a10 = ffma2(zd1, v0.x, a10);
                a11 = ffma2(zd1, v0.y, a11);
                a12 = ffma2(zd1, v1.x, a12);
                a13 = ffma2(zd1, v1.y, a13);
            }
            float d0[8], d1[8];
            unpack2f(a00, d0[0], d0[1]); unpack2f(a01, d0[2], d0[3]);
            unpack2f(a02, d0[4], d0[5]); unpack2f(a03, d0[6], d0[7]);
            unpack2f(a10, d1[0], d1[1]); unpack2f(a11, d1[2], d1[3]);
            unpack2f(a12, d1[4], d1[5]); unpack2f(a13, d1[6], d1[7]);
            int kb = ch * CHUNK + kg * 8;
            #pragma unroll
            for (int j = 0; j < 8; j++) {
                float e2 = e2s[kg * 8 + j];
                float s0 = __fsub_rn(__fadd_rn(zz0, e2), __fmul_rn(2.0f, d0[j]));
                float s1 = __fsub_rn(__fadd_rn(zz1, e2), __fmul_rn(2.0f, d1[j]));
                if (s0 < best0) { best0 = s0; bk0 = kb + j; }
                if (s1 < best1) { best1 = s1; bk1 = kb + j; }
            }
        }
    }

    // ---- epilogue: gather winners, STE-exact q, loss partial ---------------
    float sumsq = 0.f;
    {
        const float4* erow = reinterpret_cast<const float4*>(emb + (size_t)bk0 * CC);
        float* qout = out + (size_t)b0 * (CC * CHW) + hw0;
        #pragma unroll
        for (int i = 0; i < CC / 4; i++) {
            float4 e4 = __ldg(erow + i);
            float ev[4] = {e4.x, e4.y, e4.z, e4.w};
            #pragma unroll
            for (int j = 0; j < 4; j++) {
                int c = 4 * i + j;
                float dd = __fsub_rn(ev[j], zr0[c]);
                sumsq = __fadd_rn(sumsq, __fmul_rn(dd, dd));
                qout[c * CHW] = __fadd_rn(zr0[c], dd);
            }
        }
        out[IDX0 + p0] = (float)bk0;
    }
    {
        const float4* erow = reinterpret_cast<const float4*>(emb + (size_t)bk1 * CC);
        float* qout = out + (size_t)b1 * (CC * CHW) + hw1;
        #pragma unroll
        for (int i = 0; i < CC / 4; i++) {
            float4 e4 = __ldg(erow + i);
            float ev[4] = {e4.x, e4.y, e4.z, e4.w};
            #pragma unroll
            for (int j = 0; j < 4; j++) {
                int c = 4 * i + j;
                float dd = __fsub_rn(ev[j], zr1[c]);
                sumsq = __fadd_rn(sumsq, __fmul_rn(dd, dd));
                qout[c * CHW] = __fadd_rn(zr1[c], dd);
            }
        }
        out[IDX0 + p1] = (float)bk1;
    }

    #pragma unroll
    for (int o = 16; o; o >>= 1)
        sumsq += __shfl_xor_sync(0xffffffffu, sumsq, o);
    if ((threadIdx.x & 31) == 0) reds[threadIdx.x >> 5] = sumsq;
    __syncthreads();
    if (threadIdx.x == 0) {
        float s = 0.f;
        #pragma unroll
        for (int w = 0; w < NTHR / 32; w++) s += reds[w];
        g_part[blockIdx.x] = s;
    }
}

// ---- finalize: parallel deterministic loss sum -----------------------------
__global__ void __launch_bounds__(128)
vq_fin(float* __restrict__ out) {
    __shared__ float reds[4];
    const int tid = threadIdx.x;
    float s = g_part[tid];                    // NBLK == 128
    #pragma unroll
    for (int o = 16; o; o >>= 1)
        s += __shfl_xor_sync(0xffffffffu, s, o);
    if ((tid & 31) == 0) reds[tid >> 5] = s;
    __syncthreads();
    if (tid == 0) {
        float t = ((reds[0] + reds[1]) + (reds[2] + reds[3]));
        float loss = t * (1.0f / (float)Q_ELEMS);
        out[LOSS0] = loss;
        out[LOSS1] = loss;
    }
}

extern "C" void kernel_launch(void* const* d_in, const int* in_sizes, int n_in,
                              void* d_out, int out_size) {
    const float* z   = (const float*)d_in[0];
    const float* emb = (const float*)d_in[1];
    float* out = (float*)d_out;

    vq_main<<<NBLK, NTHR>>>(z, emb, out);
    vq_fin<<<1, 128>>>(out);
}

// round 14
// speedup vs baseline: 1.9812x; 1.0104x over previous
#include <cuda_runtime.h>
#include <cstdint>

// ---------------------------------------------------------------------------
// VQ-VAE VectorQuantizer, GB300 sm_103 — bit-exact fp32 reference emulation.
// R14: codebook-split scorer to fix work quantization. 2048 blocks of
// (256-pixel group x 128-code chunk); per-chunk (score,k) candidates merged
// in an emit kernel (strict < in ascending-chunk order == global first-min).
// All per-code arithmetic identical to R13 (c-ascending FFMA2 chains).
// ---------------------------------------------------------------------------

constexpr int CC     = 64;           // channels
constexpr int CHW    = 4096;         // H*W
constexpr int NPIX   = 65536;        // B*H*W
constexpr int KCB    = 1024;         // codebook entries
constexpr int CHUNK  = 128;          // codes per block
constexpr int NCHUNK = KCB / CHUNK;  // 8
constexpr int NTHR   = 128;          // threads per scorer block
constexpr int GRP    = 256;          // pixels per block (PZ=2)
constexpr int NGRP   = NPIX / GRP;   // 256
constexpr int RS     = 132;          // e_T row stride in floats (pad)

constexpr int Q_ELEMS = 4194304;
constexpr int LOSS0   = Q_ELEMS;
constexpr int LOSS1   = Q_ELEMS + 1;
constexpr int IDX0    = Q_ELEMS + 2;

__device__ float          g_cv[NCHUNK * NPIX];   // candidate scores [ch][px]
__device__ unsigned short g_ck[NCHUNK * NPIX];   // candidate global k
__device__ float          g_part[NGRP];

// ---- packed f32x2 helpers --------------------------------------------------
__device__ __forceinline__ unsigned long long pack2f(float lo, float hi) {
    unsigned long long r;
    asm("mov.b64 %0, {%1, %2};" : "=l"(r) : "f"(lo), "f"(hi));
    return r;
}
__device__ __forceinline__ void unpack2f(unsigned long long v, float& lo, float& hi) {
    asm("mov.b64 {%0, %1}, %2;" : "=f"(lo), "=f"(hi) : "l"(v));
}
__device__ __forceinline__ unsigned long long ffma2(unsigned long long a,
                                                    unsigned long long b,
                                                    unsigned long long c) {
    unsigned long long d;
    asm("fma.rn.f32x2 %0, %1, %2, %3;" : "=l"(d) : "l"(a), "l"(b), "l"(c));
    return d;
}

// ---- K1: per-chunk scorer (256 px x 128 codes per block) -------------------
__global__ __launch_bounds__(NTHR)
void vq_score(const float* __restrict__ z, const float* __restrict__ emb) {
    __shared__ __align__(16) float eT[CC * RS];   // transposed chunk [c][k]
    __shared__ float e2s[CHUNK];

    const int tid = threadIdx.x;
    const int ch  = blockIdx.x >> 8;      // 0..7 (ascending-k chunks)
    const int grp = blockIdx.x & 255;     // 0..255

    // two pixels per thread
    const int p0  = grp * GRP + tid;
    const int p1  = p0 + NTHR;
    const int b0  = p0 >> 12, hw0 = p0 & 4095;
    const int b1  = p1 >> 12, hw1 = p1 & 4095;
    const float* zp0 = z + (size_t)b0 * (CC * CHW) + hw0;
    const float* zp1 = z + (size_t)b1 * (CC * CHW) + hw1;

    float zr0[CC], zr1[CC];
    #pragma unroll
    for (int c = 0; c < CC; c++) zr0[c] = zp0[c * CHW];
    #pragma unroll
    for (int c = 0; c < CC; c++) zr1[c] = zp1[c * CHW];

    // ||z||^2 in exact reference order
    float zz0 = 0.f, zz1 = 0.f;
    #pragma unroll
    for (int c = 0; c < CC; c++) zz0 = __fadd_rn(zz0, __fmul_rn(zr0[c], zr0[c]));
    #pragma unroll
    for (int c = 0; c < CC; c++) zz1 = __fadd_rn(zz1, __fmul_rn(zr1[c], zr1[c]));

    // ---- stage + transpose this block's chunk into eT[c][k] ---------------
    const float* ebase = emb + ch * CHUNK * CC;
    #pragma unroll
    for (int it = 0; it < 4; it++) {
        int idx = tid + it * NTHR;        // 0..511
        int k0  = (idx & 31) * 4;
        int c0  = (idx >> 5) * 4;
        float4 r0 = *reinterpret_cast<const float4*>(ebase + (k0 + 0) * CC + c0);
        float4 r1 = *reinterpret_cast<const float4*>(ebase + (k0 + 1) * CC + c0);
        float4 r2 = *reinterpret_cast<const float4*>(ebase + (k0 + 2) * CC + c0);
        float4 r3 = *reinterpret_cast<const float4*>(ebase + (k0 + 3) * CC + c0);
        *reinterpret_cast<float4*>(eT + (c0 + 0) * RS + k0) = make_float4(r0.x, r1.x, r2.x, r3.x);
        *reinterpret_cast<float4*>(eT + (c0 + 1) * RS + k0) = make_float4(r0.y, r1.y, r2.y, r3.y);
        *reinterpret_cast<float4*>(eT + (c0 + 2) * RS + k0) = make_float4(r0.z, r1.z, r2.z, r3.z);
        *reinterpret_cast<float4*>(eT + (c0 + 3) * RS + k0) = make_float4(r0.w, r1.w, r2.w, r3.w);
    }
    __syncthreads();
    // exact e2 chain per code (reference mul+add order, c ascending)
    {
        float s = 0.f;
        #pragma unroll
        for (int c = 0; c < CC; c++) {
            float ev = eT[c * RS + tid];   // conflict-free (stride 132)
            s = __fadd_rn(s, __fmul_rn(ev, ev));
        }
        e2s[tid] = s;
    }
    __syncthreads();

    float best0 = 3.4e38f, best1 = 3.4e38f;
    int   bk0 = 0, bk1 = 0;

    // ---- 16 groups of 8 codes; 4 f32x2 chains per pixel -------------------
    #pragma unroll 1
    for (int kg = 0; kg < CHUNK / 8; kg++) {
        unsigned long long a00 = 0ull, a01 = 0ull, a02 = 0ull, a03 = 0ull;
        unsigned long long a10 = 0ull, a11 = 0ull, a12 = 0ull, a13 = 0ull;
        const char* rowp = reinterpret_cast<const char*>(eT + kg * 8);
        #pragma unroll
        for (int c = 0; c < CC; c++) {
            const ulonglong2* q =
                reinterpret_cast<const ulonglong2*>(rowp + c * (RS * 4));
            ulonglong2 v0 = q[0];   // codes k..k+3   (broadcast LDS.128)
            ulonglong2 v1 = q[1];   // codes k+4..k+7
            unsigned long long zd0 = pack2f(zr0[c], zr0[c]);
            unsigned long long zd1 = pack2f(zr1[c], zr1[c]);
            a00 = ffma2(zd0, v0.x, a00);
            a01 = ffma2(zd0, v0.y, a01);
            a02 = ffma2(zd0, v1.x, a02);
            a03 = ffma2(zd0, v1.y, a03);
            a10 = ffma2(zd1, v0.x, a10);
            a11 = ffma2(zd1, v0.y, a11);
            a12 = ffma2(zd1, v1.x, a12);
            a13 = ffma2(zd1, v1.y, a13);
        }
        float d0[8], d1[8];
        unpack2f(a00, d0[0], d0[1]); unpack2f(a01, d0[2], d0[3]);
        unpack2f(a02, d0[4], d0[5]); unpack2f(a03, d0[6], d0[7]);
        unpack2f(a10, d1[0], d1[1]); unpack2f(a11, d1[2], d1[3]);
        unpack2f(a12, d1[4], d1[5]); unpack2f(a13, d1[6], d1[7]);
        int kb = ch * CHUNK + kg * 8;
        #pragma unroll
        for (int j = 0; j < 8; j++) {
            float e2 = e2s[kg * 8 + j];
            float s0 = __fsub_rn(__fadd_rn(zz0, e2), __fmul_rn(2.0f, d0[j]));
            float s1 = __fsub_rn(__fadd_rn(zz1, e2), __fmul_rn(2.0f, d1[j]));
            if (s0 < best0) { best0 = s0; bk0 = kb + j; }
            if (s1 < best1) { best1 = s1; bk1 = kb + j; }
        }
    }

    // ---- per-chunk candidates ([ch][px], coalesced) ------------------------
    g_cv[ch * NPIX + p0] = best0;
    g_ck[ch * NPIX + p0] = (unsigned short)bk0;
    g_cv[ch * NPIX + p1] = best1;
    g_ck[ch * NPIX + p1] = (unsigned short)bk1;
}

// ---- K2: merge candidates + emit q/loss/idx --------------------------------
__global__ void __launch_bounds__(256)
vq_emit(const float* __restrict__ z, const float* __restrict__ emb,
        float* __restrict__ out) {
    __shared__ float reds[8];
    const int p = blockIdx.x * 256 + threadIdx.x;
    const int b = p >> 12, hw = p & 4095;

    // merge in ascending-chunk order, strict < => global first-min
    float best = g_cv[p];
    int   bk   = g_ck[p];
    #pragma unroll
    for (int q = 1; q < NCHUNK; q++) {
        float v = g_cv[q * NPIX + p];
        if (v < best) { best = v; bk = g_ck[q * NPIX + p]; }
    }

    const float4* er = reinterpret_cast<const float4*>(emb + (size_t)bk * CC);
    const float* zp = z + (size_t)b * (CC * CHW) + hw;
    float* qp = out + (size_t)b * (CC * CHW) + hw;

    float sumsq = 0.f;
    #pragma unroll
    for (int i = 0; i < 16; i++) {
        float4 e4 = __ldg(er + i);
        float ev[4] = {e4.x, e4.y, e4.z, e4.w};
        #pragma unroll
        for (int j = 0; j < 4; j++) {
            int c = 4 * i + j;
            float zv = zp[c * CHW];
            float dd = __fsub_rn(ev[j], zv);
            sumsq = __fadd_rn(sumsq, __fmul_rn(dd, dd));
            qp[c * CHW] = __fadd_rn(zv, dd);          // fl(z + fl(e - z))
        }
    }
    out[IDX0 + p] = (float)bk;

    #pragma unroll
    for (int o = 16; o; o >>= 1)
        sumsq += __shfl_xor_sync(0xffffffffu, sumsq, o);
    if ((threadIdx.x & 31) == 0) reds[threadIdx.x >> 5] = sumsq;
    __syncthreads();
    if (threadIdx.x == 0) {
        float s = 0.f;
        #pragma unroll
        for (int w = 0; w < 8; w++) s += reds[w];
        g_part[blockIdx.x] = s;
    }
}

// ---- K3: finalize: parallel deterministic loss sum -------------------------
__global__ void __launch_bounds__(256)
vq_fin(float* __restrict__ out) {
    __shared__ float reds[8];
    const int tid = threadIdx.x;
    float s = g_part[tid];                    // NGRP == 256
    #pragma unroll
    for (int o = 16; o; o >>= 1)
        s += __shfl_xor_sync(0xffffffffu, s, o);
    if ((tid & 31) == 0) reds[tid >> 5] = s;
    __syncthreads();
    if (tid == 0) {
        float t = 0.f;
        #pragma unroll
        for (int w = 0; w < 8; w++) t += reds[w];
        float loss = t * (1.0f / (float)Q_ELEMS);
        out[LOSS0] = loss;
        out[LOSS1] = loss;
    }
}

extern "C" void kernel_launch(void* const* d_in, const int* in_sizes, int n_in,
                              void* d_out, int out_size) {
    const float* z   = (const float*)d_in[0];
    const float* emb = (const float*)d_in[1];
    float* out = (float*)d_out;

    vq_score<<<NCHUNK * NGRP, NTHR>>>(z, emb);
    vq_emit<<<NGRP, 256>>>(z, emb, out);
    vq_fin<<<1, 256>>>(out);
}